// round 1
// baseline (speedup 1.0000x reference)
#include <cuda_runtime.h>

// Conv2d VALID, NCHW / OIHW, stride 1, 3x3.
// x: [32,128,64,64] f32, w: [256,128,3,3] f32, out: [32,256,62,62] f32.

#define B_  32
#define C_  128
#define H_  64
#define W_  64
#define OC_ 256
#define OH_ 62
#define OW_ 62

#define CC   16      // channel chunk per smem stage
#define OCT  64      // output channels per CTA
#define TH   8       // output tile height
#define TW   16      // output tile width
#define XSTR 19      // padded x smem row stride (floats)

__global__ __launch_bounds__(256, 2)
void conv3x3_kernel(const float* __restrict__ x,
                    const float* __restrict__ w,
                    float* __restrict__ out)
{
    __shared__ float xs[CC][TH + 2][XSTR];   // 16*10*19*4 = 12160 B
    __shared__ float ws[CC][9][OCT];         // 16*9*64*4  = 36864 B

    const int tid = threadIdx.x;
    const int ow0 = blockIdx.x * TW;
    const int oh0 = blockIdx.y * TH;
    const int b   = blockIdx.z >> 2;
    const int oc0 = (blockIdx.z & 3) * OCT;

    // warp = one oc-group (w reads become broadcast), lanes cover 128 pixels
    const int ocg = tid >> 5;          // 0..7 -> 8 output channels each
    const int pxg = tid & 31;          // 0..31 -> 4 pixels each (same row)
    const int ph  = pxg >> 2;          // 0..7
    const int pw  = (pxg & 3) << 2;    // 0,4,8,12

    float acc[8][4];
#pragma unroll
    for (int o = 0; o < 8; o++)
#pragma unroll
        for (int j = 0; j < 4; j++) acc[o][j] = 0.0f;

    for (int c0 = 0; c0 < C_; c0 += CC) {
        // ---- stage x tile: CC channels x (TH+2) rows x (TW+2) cols ----
        for (int idx = tid; idx < CC * (TH + 2) * (TW + 2); idx += 256) {
            const int c   = idx / ((TH + 2) * (TW + 2));
            const int rem = idx % ((TH + 2) * (TW + 2));
            const int r   = rem / (TW + 2);
            const int col = rem % (TW + 2);
            const int hh  = oh0 + r;
            const int wc  = ow0 + col;
            float v = 0.0f;
            if (hh < H_ && wc < W_)
                v = x[(((size_t)b * C_ + c0 + c) * H_ + hh) * W_ + wc];
            xs[c][r][col] = v;
        }
        // ---- stage w tile transposed to [c][k][oc] ----
        for (int idx = tid; idx < CC * 9 * OCT; idx += 256) {
            const int oc  = idx / (CC * 9);
            const int rem = idx % (CC * 9);       // = c*9 + k (contiguous in gmem)
            const int c   = rem / 9;
            const int k   = rem % 9;
            ws[c][k][oc] = w[(size_t)(oc0 + oc) * (C_ * 9) + (size_t)c0 * 9 + rem];
        }
        __syncthreads();

#pragma unroll 1
        for (int c = 0; c < CC; c++) {
#pragma unroll
            for (int kh = 0; kh < 3; kh++) {
                float xr[6];
#pragma unroll
                for (int j = 0; j < 6; j++) xr[j] = xs[c][ph + kh][pw + j];
#pragma unroll
                for (int kw = 0; kw < 3; kw++) {
                    const float4 w0 = *(const float4*)&ws[c][kh * 3 + kw][ocg * 8];
                    const float4 w1 = *(const float4*)&ws[c][kh * 3 + kw][ocg * 8 + 4];
                    const float wv[8] = {w0.x, w0.y, w0.z, w0.w,
                                         w1.x, w1.y, w1.z, w1.w};
#pragma unroll
                    for (int o = 0; o < 8; o++)
#pragma unroll
                        for (int j = 0; j < 4; j++)
                            acc[o][j] = fmaf(wv[o], xr[kw + j], acc[o][j]);
                }
            }
        }
        __syncthreads();
    }

    // ---- store ----
    const int oh = oh0 + ph;
    if (oh < OH_) {
#pragma unroll
        for (int o = 0; o < 8; o++) {
            const int oc = oc0 + ocg * 8 + o;
            const size_t base = (((size_t)b * OC_ + oc) * OH_ + oh) * (size_t)OW_;
#pragma unroll
            for (int j = 0; j < 4; j++) {
                const int ow = ow0 + pw + j;
                if (ow < OW_) out[base + ow] = acc[o][j];
            }
        }
    }
}

extern "C" void kernel_launch(void* const* d_in, const int* in_sizes, int n_in,
                              void* d_out, int out_size)
{
    const float* x = (const float*)d_in[0];
    const float* w = (const float*)d_in[1];
    float* out = (float*)d_out;

    dim3 grid((OW_ + TW - 1) / TW,   // 4
              (OH_ + TH - 1) / TH,   // 8
              B_ * (OC_ / OCT));     // 32 * 4 = 128
    conv3x3_kernel<<<grid, 256>>>(x, w, out);
}

// round 7
// speedup vs baseline: 4.6748x; 4.6748x over previous
#include <cuda_runtime.h>
#include <cuda_bf16.h>
#include <cuda.h>
#include <cstdint>

// x: [32,128,64,64] f32, w: [256,128,3,3] f32 -> out: [32,256,62,62] f32
#define B_   32
#define C_   128
#define HW_  4096
#define OC_  256
#define OH_  62
#define OW_  62

// ---------------- scratch (module globals; no runtime allocation) -----------
__device__ __nv_bfloat16 g_xhi[(size_t)B_ * HW_ * C_];   // NHWC bf16 hi
__device__ __nv_bfloat16 g_xlo[(size_t)B_ * HW_ * C_];   // NHWC bf16 lo
__device__ __nv_bfloat16 g_whi[9 * OC_ * C_];            // [tap][oc][c]
__device__ __nv_bfloat16 g_wlo[9 * OC_ * C_];

// ---------------- PTX helpers (sm_90-base features only) --------------------
__device__ __forceinline__ uint32_t smem_u32(const void* p) {
    uint32_t a;
    asm("{ .reg .u64 t; cvta.to.shared.u64 t, %1; cvt.u32.u64 %0, t; }"
        : "=r"(a) : "l"(p));
    return a;
}
__device__ __forceinline__ void mbar_init(uint32_t m, uint32_t cnt) {
    asm volatile("mbarrier.init.shared.b64 [%0], %1;" :: "r"(m), "r"(cnt) : "memory");
}
__device__ __forceinline__ void mbar_expect_tx(uint32_t m, uint32_t bytes) {
    asm volatile("mbarrier.arrive.expect_tx.shared.b64 _, [%0], %1;"
                 :: "r"(m), "r"(bytes) : "memory");
}
__device__ __forceinline__ void mbar_arrive(uint32_t m) {
    asm volatile("mbarrier.arrive.shared.b64 _, [%0];" :: "r"(m) : "memory");
}
__device__ __forceinline__ void mbar_wait(uint32_t m, uint32_t phase) {
    asm volatile(
        "{\n\t.reg .pred P;\n\t"
        "LW%=:\n\t"
        "mbarrier.try_wait.parity.acquire.cta.shared::cta.b64 P, [%0], %1, 0x989680;\n\t"
        "@P bra.uni LD%=;\n\t"
        "bra.uni LW%=;\n\t"
        "LD%=:\n\t}"
        :: "r"(m), "r"(phase) : "memory");
}
__device__ __forceinline__ void tma2d(uint32_t dst, const CUtensorMap* map,
                                      int cx, int cy, uint32_t mbar) {
    asm volatile(
        "cp.async.bulk.tensor.2d.shared::cta.global.tile.mbarrier::complete_tx::bytes "
        "[%0], [%1, {%2, %3}], [%4];"
        :: "r"(dst), "l"(map), "r"(cx), "r"(cy), "r"(mbar) : "memory");
}
__device__ __forceinline__ void ldsm4(uint32_t& r0, uint32_t& r1, uint32_t& r2,
                                      uint32_t& r3, uint32_t addr) {
    asm volatile("ldmatrix.sync.aligned.m8n8.x4.shared.b16 {%0,%1,%2,%3}, [%4];"
                 : "=r"(r0), "=r"(r1), "=r"(r2), "=r"(r3) : "r"(addr));
}
__device__ __forceinline__ void mma16816(float* d, const uint32_t* a, const uint32_t* b) {
    asm volatile(
        "mma.sync.aligned.m16n8k16.row.col.f32.bf16.bf16.f32 "
        "{%0,%1,%2,%3}, {%4,%5,%6,%7}, {%8,%9}, {%0,%1,%2,%3};"
        : "+f"(d[0]), "+f"(d[1]), "+f"(d[2]), "+f"(d[3])
        : "r"(a[0]), "r"(a[1]), "r"(a[2]), "r"(a[3]), "r"(b[0]), "r"(b[1]));
}
__device__ __forceinline__ uint32_t swz(uint32_t off) {   // SW128: off in 128B rows
    return off ^ ((off >> 3) & 0x70);
}

// ---------------- prologue: transpose + bf16 split --------------------------
__global__ void xform_x(const float* __restrict__ x) {
    __shared__ float t[32][33];
    const int b  = blockIdx.z;
    const int c0 = blockIdx.y * 32;
    const int p0 = blockIdx.x * 32;
    const int tx = threadIdx.x, ty = threadIdx.y;
    t[ty][tx] = x[((size_t)b * C_ + (c0 + ty)) * HW_ + (p0 + tx)];
    __syncthreads();
    const float v = t[tx][ty];
    const __nv_bfloat16 h = __float2bfloat16(v);
    const __nv_bfloat16 l = __float2bfloat16(v - __bfloat162float(h));
    const size_t o = ((size_t)b * HW_ + (p0 + ty)) * C_ + (c0 + tx);
    g_xhi[o] = h;
    g_xlo[o] = l;
}

__global__ void xform_w(const float* __restrict__ w) {
    const int idx = blockIdx.x * 256 + threadIdx.x;
    if (idx >= OC_ * C_ * 9) return;
    const float v = w[idx];
    const int r  = idx % 9;
    const int c  = (idx / 9) % C_;
    const int oc = idx / (9 * C_);
    const __nv_bfloat16 h = __float2bfloat16(v);
    const __nv_bfloat16 l = __float2bfloat16(v - __bfloat162float(h));
    const int o = (r * OC_ + oc) * C_ + c;
    g_whi[o] = h;
    g_wlo[o] = l;
}

// ---------------- main implicit-GEMM kernel (HMMA) ---------------------------
// CTA: M=128 (2 out rows x 64 cols linearized), N=128 oc. 18 K-chunks of 64.
#define NCH      18
#define TILE_B   16384                 // 128 rows x 64 bf16 (SW128)
#define STAGE_B  65536                 // xh, xl, wh, wl tiles
#define DATA_OFF 1024
#define EPS      132                   // epilogue smem row stride (floats)

__global__ __launch_bounds__(256, 1)
void conv_mma(const __grid_constant__ CUtensorMap mxh,
              const __grid_constant__ CUtensorMap mxl,
              const __grid_constant__ CUtensorMap mwh,
              const __grid_constant__ CUtensorMap mwl,
              float* __restrict__ out)
{
    extern __shared__ char smem[];
    const uint32_t sb = smem_u32(smem);
    const int tid = threadIdx.x, wid = tid >> 5, lane = tid & 31;

    const uint32_t FULL  = sb;         // full[s]  = FULL  + 8*s
    const uint32_t EMPTY = sb + 16;    // empty[s] = EMPTY + 8*s

    const int mg  = blockIdx.x;            // 992 = 32 b * 31 row-pairs
    const int b   = mg / 31;
    const int i0  = (mg % 31) * 2;
    const int oc0 = blockIdx.y * 128;

    if (tid == 0) {
        for (int s = 0; s < 2; s++) {
            mbar_init(FULL + 8 * s, 1);
            mbar_init(EMPTY + 8 * s, 256);
        }
    }
    __syncthreads();

    // warp tile: m0 = 64*(wid&1), n0 = 32*(wid>>1)
    const int m0 = (wid & 1) * 64;
    const int n0 = (wid >> 1) * 32;

    float acc[4][4][4];
#pragma unroll
    for (int mt = 0; mt < 4; mt++)
#pragma unroll
        for (int nt = 0; nt < 4; nt++)
#pragma unroll
            for (int k = 0; k < 4; k++) acc[mt][nt][k] = 0.0f;

    // ldmatrix intra-tile offsets (swizzled), per lane
    const uint32_t a_row = (uint32_t)(m0 + (lane & 15));
    const uint32_t a_cb  = (uint32_t)((lane >> 4) * 16);
    const uint32_t b_row = (uint32_t)(n0 + (lane & 7) + ((lane >> 4) << 3));
    const uint32_t b_cb  = (uint32_t)(((lane >> 3) & 1) * 16);

    auto issue_chunk = [&](int ch, int s) {
        const uint32_t st = sb + DATA_OFF + (uint32_t)s * STAGE_B;
        const int r   = ch >> 1;
        const int c0  = (ch & 1) * 64;
        const int kh  = r / 3, kw = r % 3;
        const int py  = b * HW_ + (i0 + kh) * 64 + kw;
        const int wy  = r * 256 + oc0;
        mbar_expect_tx(FULL + 8 * s, STAGE_B);
        tma2d(st + 0 * TILE_B, &mxh, c0, py, FULL + 8 * s);
        tma2d(st + 1 * TILE_B, &mxl, c0, py, FULL + 8 * s);
        tma2d(st + 2 * TILE_B, &mwh, c0, wy, FULL + 8 * s);
        tma2d(st + 3 * TILE_B, &mwl, c0, wy, FULL + 8 * s);
    };

    if (tid == 0) { issue_chunk(0, 0); issue_chunk(1, 1); }

    int fph[2] = {0, 0}, eph[2] = {0, 0};

    for (int ch = 0; ch < NCH; ch++) {
        const int s = ch & 1;
        mbar_wait(FULL + 8 * s, fph[s]); fph[s] ^= 1;

        const uint32_t st = sb + DATA_OFF + (uint32_t)s * STAGE_B;
        const uint32_t tAH = st, tAL = st + TILE_B, tWH = st + 2 * TILE_B,
                       tWL = st + 3 * TILE_B;

#pragma unroll
        for (int ks = 0; ks < 4; ks++) {
            const uint32_t k2 = (uint32_t)(ks * 32);   // k0*2 bytes
            uint32_t ah[4][4], al[4][4], bh[8], bl[8];
#pragma unroll
            for (int mt = 0; mt < 4; mt++) {
                const uint32_t off = swz((a_row + mt * 16) * 128 + k2 + a_cb);
                ldsm4(ah[mt][0], ah[mt][1], ah[mt][2], ah[mt][3], tAH + off);
                ldsm4(al[mt][0], al[mt][1], al[mt][2], al[mt][3], tAL + off);
            }
#pragma unroll
            for (int g = 0; g < 2; g++) {
                const uint32_t off = swz((b_row + g * 16) * 128 + k2 + b_cb);
                ldsm4(bh[g * 4 + 0], bh[g * 4 + 1], bh[g * 4 + 2], bh[g * 4 + 3], tWH + off);
                ldsm4(bl[g * 4 + 0], bl[g * 4 + 1], bl[g * 4 + 2], bl[g * 4 + 3], tWL + off);
            }
#pragma unroll
            for (int mt = 0; mt < 4; mt++)
#pragma unroll
                for (int nt = 0; nt < 4; nt++) {
                    mma16816(acc[mt][nt], ah[mt], &bh[nt * 2]);
                    mma16816(acc[mt][nt], ah[mt], &bl[nt * 2]);
                    mma16816(acc[mt][nt], al[mt], &bh[nt * 2]);
                }
        }

        mbar_arrive(EMPTY + 8 * s);
        if (tid == 0 && ch + 2 < NCH) {
            mbar_wait(EMPTY + 8 * s, eph[s]); eph[s] ^= 1;
            issue_chunk(ch + 2, s);
        }
    }

    // ---------------- epilogue: regs -> smem transpose -> coalesced GMEM ----
    __syncthreads();
    float* epi = (float*)(smem + DATA_OFF);
#pragma unroll
    for (int mt = 0; mt < 4; mt++) {
        const int mr = m0 + mt * 16 + (lane >> 2);
#pragma unroll
        for (int nt = 0; nt < 4; nt++) {
            const int nc = n0 + nt * 8 + (lane & 3) * 2;
            epi[nc * EPS + mr]           = acc[mt][nt][0];
            epi[(nc + 1) * EPS + mr]     = acc[mt][nt][1];
            epi[nc * EPS + mr + 8]       = acc[mt][nt][2];
            epi[(nc + 1) * EPS + mr + 8] = acc[mt][nt][3];
        }
    }
    __syncthreads();

    const int g = tid >> 7;          // 0..1
    const int m = tid & 127;         // 0..127
    const int rrow = m >> 6, j = m & 63;
    if (j < OW_) {
        const int i = i0 + rrow;
#pragma unroll 4
        for (int n = g; n < 128; n += 2) {
            out[((size_t)(b * OC_ + oc0 + n) * OH_ + i) * OW_ + j] = epi[n * EPS + m];
        }
    }
}

// ---------------- host launcher ---------------------------------------------
typedef CUresult (*EncodeFn)(CUtensorMap*, CUtensorMapDataType, cuuint32_t, void*,
                             const cuuint64_t*, const cuuint64_t*, const cuuint32_t*,
                             const cuuint32_t*, CUtensorMapInterleave, CUtensorMapSwizzle,
                             CUtensorMapL2promotion, CUtensorMapFloatOOBfill);

extern "C" void kernel_launch(void* const* d_in, const int* in_sizes, int n_in,
                              void* d_out, int out_size)
{
    const float* x = (const float*)d_in[0];
    const float* w = (const float*)d_in[1];
    float* out = (float*)d_out;

    void *pxh, *pxl, *pwh, *pwl;
    cudaGetSymbolAddress(&pxh, g_xhi);
    cudaGetSymbolAddress(&pxl, g_xlo);
    cudaGetSymbolAddress(&pwh, g_whi);
    cudaGetSymbolAddress(&pwl, g_wlo);

    EncodeFn enc = nullptr;
    cudaDriverEntryPointQueryResult qr;
    cudaGetDriverEntryPointByVersion("cuTensorMapEncodeTiled", (void**)&enc, 12000,
                                     cudaEnableDefault, &qr);

    CUtensorMap mxh, mxl, mwh, mwl;
    {
        cuuint64_t dims[2]    = {128, (cuuint64_t)B_ * HW_};
        cuuint64_t strides[1] = {256};
        cuuint32_t box[2]     = {64, 128};
        cuuint32_t es[2]      = {1, 1};
        enc(&mxh, CU_TENSOR_MAP_DATA_TYPE_BFLOAT16, 2, pxh, dims, strides, box, es,
            CU_TENSOR_MAP_INTERLEAVE_NONE, CU_TENSOR_MAP_SWIZZLE_128B,
            CU_TENSOR_MAP_L2_PROMOTION_L2_128B, CU_TENSOR_MAP_FLOAT_OOB_FILL_NONE);
        enc(&mxl, CU_TENSOR_MAP_DATA_TYPE_BFLOAT16, 2, pxl, dims, strides, box, es,
            CU_TENSOR_MAP_INTERLEAVE_NONE, CU_TENSOR_MAP_SWIZZLE_128B,
            CU_TENSOR_MAP_L2_PROMOTION_L2_128B, CU_TENSOR_MAP_FLOAT_OOB_FILL_NONE);
    }
    {
        cuuint64_t dims[2]    = {128, 9 * 256};
        cuuint64_t strides[1] = {256};
        cuuint32_t box[2]     = {64, 128};
        cuuint32_t es[2]      = {1, 1};
        enc(&mwh, CU_TENSOR_MAP_DATA_TYPE_BFLOAT16, 2, pwh, dims, strides, box, es,
            CU_TENSOR_MAP_INTERLEAVE_NONE, CU_TENSOR_MAP_SWIZZLE_128B,
            CU_TENSOR_MAP_L2_PROMOTION_L2_128B, CU_TENSOR_MAP_FLOAT_OOB_FILL_NONE);
        enc(&mwl, CU_TENSOR_MAP_DATA_TYPE_BFLOAT16, 2, pwl, dims, strides, box, es,
            CU_TENSOR_MAP_INTERLEAVE_NONE, CU_TENSOR_MAP_SWIZZLE_128B,
            CU_TENSOR_MAP_L2_PROMOTION_L2_128B, CU_TENSOR_MAP_FLOAT_OOB_FILL_NONE);
    }

    xform_x<<<dim3(128, 4, 32), dim3(32, 32)>>>(x);
    xform_w<<<(OC_ * C_ * 9 + 255) / 256, 256>>>(w);

    const int smem_bytes = DATA_OFF + 2 * STAGE_B;   // 132096
    cudaFuncSetAttribute(conv_mma, cudaFuncAttributeMaxDynamicSharedMemorySize,
                         smem_bytes);
    conv_mma<<<dim3(992, 2, 1), 256, smem_bytes>>>(mxh, mxl, mwh, mwl, out);
}

// round 12
// speedup vs baseline: 4.7500x; 1.0161x over previous
#include <cuda_runtime.h>
#include <cuda_bf16.h>
#include <cuda.h>
#include <cstdint>

// x: [32,128,64,64] f32, w: [256,128,3,3] f32 -> out: [32,256,62,62] f32
#define B_   32
#define C_   128
#define HW_  4096
#define OC_  256
#define OH_  62
#define OW_  62

// ---------------- scratch (module globals; no runtime allocation) -----------
__device__ __nv_bfloat16 g_xhi[(size_t)B_ * HW_ * C_];   // NHWC bf16 hi
__device__ __nv_bfloat16 g_xlo[(size_t)B_ * HW_ * C_];   // NHWC bf16 lo
__device__ __nv_bfloat16 g_whi[9 * OC_ * C_];            // [tap][oc][c]
__device__ __nv_bfloat16 g_wlo[9 * OC_ * C_];

// ---------------- PTX helpers (sm_90-base features only) --------------------
__device__ __forceinline__ uint32_t smem_u32(const void* p) {
    uint32_t a;
    asm("{ .reg .u64 t; cvta.to.shared.u64 t, %1; cvt.u32.u64 %0, t; }"
        : "=r"(a) : "l"(p));
    return a;
}
__device__ __forceinline__ void mbar_init(uint32_t m, uint32_t cnt) {
    asm volatile("mbarrier.init.shared.b64 [%0], %1;" :: "r"(m), "r"(cnt) : "memory");
}
__device__ __forceinline__ void mbar_expect_tx(uint32_t m, uint32_t bytes) {
    asm volatile("mbarrier.arrive.expect_tx.shared.b64 _, [%0], %1;"
                 :: "r"(m), "r"(bytes) : "memory");
}
__device__ __forceinline__ void mbar_arrive(uint32_t m) {
    asm volatile("mbarrier.arrive.shared.b64 _, [%0];" :: "r"(m) : "memory");
}
__device__ __forceinline__ void mbar_wait(uint32_t m, uint32_t phase) {
    asm volatile(
        "{\n\t.reg .pred P;\n\t"
        "LW%=:\n\t"
        "mbarrier.try_wait.parity.acquire.cta.shared::cta.b64 P, [%0], %1, 0x989680;\n\t"
        "@P bra.uni LD%=;\n\t"
        "bra.uni LW%=;\n\t"
        "LD%=:\n\t}"
        :: "r"(m), "r"(phase) : "memory");
}
__device__ __forceinline__ void tma2d(uint32_t dst, const CUtensorMap* map,
                                      int cx, int cy, uint32_t mbar) {
    asm volatile(
        "cp.async.bulk.tensor.2d.shared::cta.global.tile.mbarrier::complete_tx::bytes "
        "[%0], [%1, {%2, %3}], [%4];"
        :: "r"(dst), "l"(map), "r"(cx), "r"(cy), "r"(mbar) : "memory");
}
__device__ __forceinline__ void ldsm4(uint32_t& r0, uint32_t& r1, uint32_t& r2,
                                      uint32_t& r3, uint32_t addr) {
    asm volatile("ldmatrix.sync.aligned.m8n8.x4.shared.b16 {%0,%1,%2,%3}, [%4];"
                 : "=r"(r0), "=r"(r1), "=r"(r2), "=r"(r3) : "r"(addr));
}
__device__ __forceinline__ void mma16816(float* d, const uint32_t* a, const uint32_t* b) {
    asm volatile(
        "mma.sync.aligned.m16n8k16.row.col.f32.bf16.bf16.f32 "
        "{%0,%1,%2,%3}, {%4,%5,%6,%7}, {%8,%9}, {%0,%1,%2,%3};"
        : "+f"(d[0]), "+f"(d[1]), "+f"(d[2]), "+f"(d[3])
        : "r"(a[0]), "r"(a[1]), "r"(a[2]), "r"(a[3]), "r"(b[0]), "r"(b[1]));
}
__device__ __forceinline__ uint32_t swz(uint32_t off) {   // SW128: off in 128B rows
    return off ^ ((off >> 3) & 0x70);
}

// ---------------- prologue: transpose + bf16 split (vectorized stores) ------
// Block: 32x32 threads, tile = 64 channels x 32 pixels. Write phase packs two
// consecutive channels into one uint32 -> 128B contiguous per warp per array.
__global__ void xform_x(const float* __restrict__ x) {
    __shared__ float t[64][33];
    const int b  = blockIdx.z;
    const int c0 = blockIdx.y * 64;
    const int p0 = blockIdx.x * 32;
    const int tx = threadIdx.x, ty = threadIdx.y;

    t[ty][tx]      = x[((size_t)b * C_ + (c0 + ty)) * HW_ + (p0 + tx)];
    t[ty + 32][tx] = x[((size_t)b * C_ + (c0 + ty + 32)) * HW_ + (p0 + tx)];
    __syncthreads();

    const float v0 = t[2 * tx][ty];
    const float v1 = t[2 * tx + 1][ty];
    const __nv_bfloat16 h0 = __float2bfloat16(v0);
    const __nv_bfloat16 h1 = __float2bfloat16(v1);
    const __nv_bfloat16 l0 = __float2bfloat16(v0 - __bfloat162float(h0));
    const __nv_bfloat16 l1 = __float2bfloat16(v1 - __bfloat162float(h1));
    const uint32_t hp = (uint32_t)__bfloat16_as_ushort(h0) |
                        ((uint32_t)__bfloat16_as_ushort(h1) << 16);
    const uint32_t lp = (uint32_t)__bfloat16_as_ushort(l0) |
                        ((uint32_t)__bfloat16_as_ushort(l1) << 16);
    const size_t o32 = (((size_t)b * HW_ + (p0 + ty)) * C_ + c0) / 2 + tx;
    ((uint32_t*)g_xhi)[o32] = hp;
    ((uint32_t*)g_xlo)[o32] = lp;
}

__global__ void xform_w(const float* __restrict__ w) {
    const int idx = blockIdx.x * 256 + threadIdx.x;
    if (idx >= OC_ * C_ * 9) return;
    const float v = w[idx];
    const int r  = idx % 9;
    const int c  = (idx / 9) % C_;
    const int oc = idx / (9 * C_);
    const __nv_bfloat16 h = __float2bfloat16(v);
    const __nv_bfloat16 l = __float2bfloat16(v - __bfloat162float(h));
    const int o = (r * OC_ + oc) * C_ + c;
    g_whi[o] = h;
    g_wlo[o] = l;
}

// ---------------- main implicit-GEMM kernel (HMMA, 3-stage pipeline) ---------
#define NCH      18
#define NSTG     3
#define TILE_B   16384                 // 128 rows x 64 bf16 (SW128)
#define STAGE_B  65536                 // xh, xl, wh, wl tiles
#define DATA_OFF 1024
#define EPS      132                   // epilogue smem row stride (floats)

__global__ __launch_bounds__(256, 1)
void conv_mma(const __grid_constant__ CUtensorMap mxh,
              const __grid_constant__ CUtensorMap mxl,
              const __grid_constant__ CUtensorMap mwh,
              const __grid_constant__ CUtensorMap mwl,
              float* __restrict__ out)
{
    extern __shared__ char smem[];
    const uint32_t sb = smem_u32(smem);
    const int tid = threadIdx.x, wid = tid >> 5, lane = tid & 31;

    const uint32_t FULL  = sb;         // full[s]  = FULL  + 8*s
    const uint32_t EMPTY = sb + 32;    // empty[s] = EMPTY + 8*s

    const int mg  = blockIdx.x;            // 992 = 32 b * 31 row-pairs
    const int b   = mg / 31;
    const int i0  = (mg % 31) * 2;
    const int oc0 = blockIdx.y * 128;

    if (tid == 0) {
        for (int s = 0; s < NSTG; s++) {
            mbar_init(FULL + 8 * s, 1);
            mbar_init(EMPTY + 8 * s, 256);
        }
    }
    __syncthreads();

    const int m0 = (wid & 1) * 64;
    const int n0 = (wid >> 1) * 32;

    float acc[4][4][4];
#pragma unroll
    for (int mt = 0; mt < 4; mt++)
#pragma unroll
        for (int nt = 0; nt < 4; nt++)
#pragma unroll
            for (int k = 0; k < 4; k++) acc[mt][nt][k] = 0.0f;

    const uint32_t a_row = (uint32_t)(m0 + (lane & 15));
    const uint32_t a_cb  = (uint32_t)((lane >> 4) * 16);
    const uint32_t b_row = (uint32_t)(n0 + (lane & 7) + ((lane >> 4) << 3));
    const uint32_t b_cb  = (uint32_t)(((lane >> 3) & 1) * 16);

    auto issue_chunk = [&](int ch, int s) {
        const uint32_t st = sb + DATA_OFF + (uint32_t)s * STAGE_B;
        const int r   = ch >> 1;
        const int c0  = (ch & 1) * 64;
        const int kh  = r / 3, kw = r % 3;
        const int py  = b * HW_ + (i0 + kh) * 64 + kw;
        const int wy  = r * 256 + oc0;
        mbar_expect_tx(FULL + 8 * s, STAGE_B);
        tma2d(st + 0 * TILE_B, &mxh, c0, py, FULL + 8 * s);
        tma2d(st + 1 * TILE_B, &mxl, c0, py, FULL + 8 * s);
        tma2d(st + 2 * TILE_B, &mwh, c0, wy, FULL + 8 * s);
        tma2d(st + 3 * TILE_B, &mwl, c0, wy, FULL + 8 * s);
    };

    if (tid == 0) {
        issue_chunk(0, 0);
        issue_chunk(1, 1);
        issue_chunk(2, 2);
    }

    int fph[NSTG] = {0, 0, 0}, eph[NSTG] = {0, 0, 0};

    for (int ch = 0; ch < NCH; ch++) {
        const int s = ch % NSTG;
        mbar_wait(FULL + 8 * s, fph[s]); fph[s] ^= 1;

        const uint32_t st = sb + DATA_OFF + (uint32_t)s * STAGE_B;
        const uint32_t tAH = st, tAL = st + TILE_B, tWH = st + 2 * TILE_B,
                       tWL = st + 3 * TILE_B;

#pragma unroll
        for (int ks = 0; ks < 4; ks++) {
            const uint32_t k2 = (uint32_t)(ks * 32);   // k0*2 bytes
            uint32_t ah[4][4], al[4][4], bh[8], bl[8];
#pragma unroll
            for (int g = 0; g < 2; g++) {
                const uint32_t off = swz((b_row + g * 16) * 128 + k2 + b_cb);
                ldsm4(bh[g * 4 + 0], bh[g * 4 + 1], bh[g * 4 + 2], bh[g * 4 + 3], tWH + off);
                ldsm4(bl[g * 4 + 0], bl[g * 4 + 1], bl[g * 4 + 2], bl[g * 4 + 3], tWL + off);
            }
#pragma unroll
            for (int mt = 0; mt < 4; mt++) {
                const uint32_t off = swz((a_row + mt * 16) * 128 + k2 + a_cb);
                ldsm4(ah[mt][0], ah[mt][1], ah[mt][2], ah[mt][3], tAH + off);
                ldsm4(al[mt][0], al[mt][1], al[mt][2], al[mt][3], tAL + off);
            }
#pragma unroll
            for (int mt = 0; mt < 4; mt++)
#pragma unroll
                for (int nt = 0; nt < 4; nt++) {
                    mma16816(acc[mt][nt], ah[mt], &bh[nt * 2]);
                    mma16816(acc[mt][nt], ah[mt], &bl[nt * 2]);
                    mma16816(acc[mt][nt], al[mt], &bh[nt * 2]);
                }
        }

        mbar_arrive(EMPTY + 8 * s);
        if (tid == 0 && ch + NSTG < NCH) {
            mbar_wait(EMPTY + 8 * s, eph[s]); eph[s] ^= 1;
            issue_chunk(ch + NSTG, s);
        }
    }

    // ---------------- epilogue: regs -> smem transpose -> coalesced GMEM ----
    __syncthreads();
    float* epi = (float*)(smem + DATA_OFF);
#pragma unroll
    for (int mt = 0; mt < 4; mt++) {
        const int mr = m0 + mt * 16 + (lane >> 2);
#pragma unroll
        for (int nt = 0; nt < 4; nt++) {
            const int nc = n0 + nt * 8 + (lane & 3) * 2;
            epi[nc * EPS + mr]           = acc[mt][nt][0];
            epi[(nc + 1) * EPS + mr]     = acc[mt][nt][1];
            epi[nc * EPS + mr + 8]       = acc[mt][nt][2];
            epi[(nc + 1) * EPS + mr + 8] = acc[mt][nt][3];
        }
    }
    __syncthreads();

    const int g = tid >> 7;          // 0..1
    const int m = tid & 127;         // 0..127
    const int rrow = m >> 6, j = m & 63;
    if (j < OW_) {
        const int i = i0 + rrow;
#pragma unroll 4
        for (int n = g; n < 128; n += 2) {
            out[((size_t)(b * OC_ + oc0 + n) * OH_ + i) * OW_ + j] = epi[n * EPS + m];
        }
    }
}

// ---------------- host launcher ---------------------------------------------
typedef CUresult (*EncodeFn)(CUtensorMap*, CUtensorMapDataType, cuuint32_t, void*,
                             const cuuint64_t*, const cuuint64_t*, const cuuint32_t*,
                             const cuuint32_t*, CUtensorMapInterleave, CUtensorMapSwizzle,
                             CUtensorMapL2promotion, CUtensorMapFloatOOBfill);

extern "C" void kernel_launch(void* const* d_in, const int* in_sizes, int n_in,
                              void* d_out, int out_size)
{
    const float* x = (const float*)d_in[0];
    const float* w = (const float*)d_in[1];
    float* out = (float*)d_out;

    void *pxh, *pxl, *pwh, *pwl;
    cudaGetSymbolAddress(&pxh, g_xhi);
    cudaGetSymbolAddress(&pxl, g_xlo);
    cudaGetSymbolAddress(&pwh, g_whi);
    cudaGetSymbolAddress(&pwl, g_wlo);

    EncodeFn enc = nullptr;
    cudaDriverEntryPointQueryResult qr;
    cudaGetDriverEntryPointByVersion("cuTensorMapEncodeTiled", (void**)&enc, 12000,
                                     cudaEnableDefault, &qr);

    CUtensorMap mxh, mxl, mwh, mwl;
    {
        cuuint64_t dims[2]    = {128, (cuuint64_t)B_ * HW_};
        cuuint64_t strides[1] = {256};
        cuuint32_t box[2]     = {64, 128};
        cuuint32_t es[2]      = {1, 1};
        enc(&mxh, CU_TENSOR_MAP_DATA_TYPE_BFLOAT16, 2, pxh, dims, strides, box, es,
            CU_TENSOR_MAP_INTERLEAVE_NONE, CU_TENSOR_MAP_SWIZZLE_128B,
            CU_TENSOR_MAP_L2_PROMOTION_L2_128B, CU_TENSOR_MAP_FLOAT_OOB_FILL_NONE);
        enc(&mxl, CU_TENSOR_MAP_DATA_TYPE_BFLOAT16, 2, pxl, dims, strides, box, es,
            CU_TENSOR_MAP_INTERLEAVE_NONE, CU_TENSOR_MAP_SWIZZLE_128B,
            CU_TENSOR_MAP_L2_PROMOTION_L2_128B, CU_TENSOR_MAP_FLOAT_OOB_FILL_NONE);
    }
    {
        cuuint64_t dims[2]    = {128, 9 * 256};
        cuuint64_t strides[1] = {256};
        cuuint32_t box[2]     = {64, 128};
        cuuint32_t es[2]      = {1, 1};
        enc(&mwh, CU_TENSOR_MAP_DATA_TYPE_BFLOAT16, 2, pwh, dims, strides, box, es,
            CU_TENSOR_MAP_INTERLEAVE_NONE, CU_TENSOR_MAP_SWIZZLE_128B,
            CU_TENSOR_MAP_L2_PROMOTION_L2_128B, CU_TENSOR_MAP_FLOAT_OOB_FILL_NONE);
        enc(&mwl, CU_TENSOR_MAP_DATA_TYPE_BFLOAT16, 2, pwl, dims, strides, box, es,
            CU_TENSOR_MAP_INTERLEAVE_NONE, CU_TENSOR_MAP_SWIZZLE_128B,
            CU_TENSOR_MAP_L2_PROMOTION_L2_128B, CU_TENSOR_MAP_FLOAT_OOB_FILL_NONE);
    }

    xform_x<<<dim3(128, 2, 32), dim3(32, 32)>>>(x);
    xform_w<<<(OC_ * C_ * 9 + 255) / 256, 256>>>(w);

    const int smem_bytes = DATA_OFF + NSTG * STAGE_B;   // 197632
    cudaFuncSetAttribute(conv_mma, cudaFuncAttributeMaxDynamicSharedMemorySize,
                         smem_bytes);
    conv_mma<<<dim3(992, 2, 1), 256, smem_bytes>>>(mxh, mxl, mwh, mwl, out);
}